// round 3
// baseline (speedup 1.0000x reference)
#include <cuda_runtime.h>
#include <stdint.h>

#define NUM_USER 200000
#define NUM_ITEM 100000
#define NUM_NODES 300000
#define DIM 64
#define BATCH 8192
#define NODE_FLOATS (NUM_NODES * DIM)     // 19,200,000 floats
#define NODE_F4 (NODE_FLOATS / 4)         // 4,800,000 float4
#define MAX_EDGES 2000000
#define OUT_BLK (BATCH * DIM)             // 524,288

// JAX threefry mode: 1 = partitionable (JAX >= 0.5 default), 0 = original
#define JAX_PARTITIONABLE 1

// ---------------- scratch (device globals; no cudaMalloc allowed) ----------
__device__ float g_x0[NODE_FLOATS];
__device__ float g_x1[NODE_FLOATS];
__device__ float g_acc[NODE_FLOATS];
__device__ float g_vals[MAX_EDGES];

// ---------------- threefry2x32 (exact JAX key schedule) --------------------
#define TF_ROUND(x0, x1, r)                         \
    {                                               \
        x0 += x1;                                   \
        x1 = (x1 << (r)) | (x1 >> (32 - (r)));      \
        x1 ^= x0;                                   \
    }

__host__ __device__ __forceinline__ void tf2x32(uint32_t k0, uint32_t k1,
                                                uint32_t& x0, uint32_t& x1) {
    uint32_t k2 = k0 ^ k1 ^ 0x1BD11BDAu;
    x0 += k0; x1 += k1;
    TF_ROUND(x0, x1, 13) TF_ROUND(x0, x1, 15) TF_ROUND(x0, x1, 26) TF_ROUND(x0, x1, 6)
    x0 += k1; x1 += k2 + 1u;
    TF_ROUND(x0, x1, 17) TF_ROUND(x0, x1, 29) TF_ROUND(x0, x1, 16) TF_ROUND(x0, x1, 24)
    x0 += k2; x1 += k0 + 2u;
    TF_ROUND(x0, x1, 13) TF_ROUND(x0, x1, 15) TF_ROUND(x0, x1, 26) TF_ROUND(x0, x1, 6)
    x0 += k0; x1 += k1 + 3u;
    TF_ROUND(x0, x1, 17) TF_ROUND(x0, x1, 29) TF_ROUND(x0, x1, 16) TF_ROUND(x0, x1, 24)
    x0 += k1; x1 += k2 + 4u;
    TF_ROUND(x0, x1, 13) TF_ROUND(x0, x1, 15) TF_ROUND(x0, x1, 26) TF_ROUND(x0, x1, 6)
    x0 += k2; x1 += k0 + 5u;
}

// 32-bit random bits for flat index i (partitionable: counts=(hi,lo)=(0,i), out=w0^w1)
__device__ __forceinline__ uint32_t rbits_part(uint32_t k0, uint32_t k1, uint32_t idx) {
    uint32_t x0 = 0u, x1 = idx;
    tf2x32(k0, k1, x0, x1);
    return x0 ^ x1;
}

#if !JAX_PARTITIONABLE
// original mode: counts = iota(N); x0 half = [0,N/2), x1 half = [N/2,N)
__device__ __forceinline__ uint32_t rbits_orig(uint32_t k0, uint32_t k1,
                                               uint32_t idx, uint32_t n) {
    uint32_t half = (n + 1u) / 2u;
    uint32_t x0, x1;
    int second = idx >= half;
    if (second) { x0 = idx - half; x1 = idx; }
    else        { x0 = idx;        x1 = idx + half; }
    tf2x32(k0, k1, x0, x1);
    return second ? x1 : x0;
}
#define RBITS(k0, k1, idx, n) rbits_orig(k0, k1, (uint32_t)(idx), (uint32_t)(n))
#else
#define RBITS(k0, k1, idx, n) rbits_part(k0, k1, (uint32_t)(idx))
#endif

// ---------------- kernels --------------------------------------------------

// x0 = concat(user_emb, item_emb); acc = same; x1 = 0
__global__ void __launch_bounds__(256) k_init(const float4* __restrict__ ue,
                                              const float4* __restrict__ ie) {
    int i = blockIdx.x * blockDim.x + threadIdx.x;
    if (i >= NODE_F4) return;
    float4 v = (i < NUM_USER * (DIM / 4)) ? __ldg(&ue[i]) : __ldg(&ie[i - NUM_USER * (DIM / 4)]);
    ((float4*)g_x0)[i] = v;
    ((float4*)g_acc)[i] = v;
    ((float4*)g_x1)[i] = make_float4(0.f, 0.f, 0.f, 0.f);
}

// edge dropout: keep iff uniform >= 0.5 iff top bit of bits set; scale 1/(1-p)=2
__global__ void __launch_bounds__(256) k_edges(const float* __restrict__ adj_vals,
                                               int n_edges, uint32_t k0, uint32_t k1) {
    int e = blockIdx.x * blockDim.x + threadIdx.x;
    if (e >= n_edges) return;
    uint32_t bits = RBITS(k0, k1, e, n_edges);
    g_vals[e] = (bits >> 31) ? __ldg(&adj_vals[e]) * 2.0f : 0.0f;
}

// scatter SPMM: 16 threads per edge, one float4 atomic each. dir: 0 = x0->x1, 1 = x1->x0
__global__ void __launch_bounds__(512) k_spmm(const int* __restrict__ rows,
                                              const int* __restrict__ cols,
                                              int n_edges, int dir) {
    long long t = (long long)blockIdx.x * blockDim.x + threadIdx.x;
    int e = (int)(t >> 4);
    if (e >= n_edges) return;
    float v = __ldg(&g_vals[e]);
    if (v == 0.0f) return;
    int c = (int)(t & 15);
    const float4* __restrict__ xin = dir ? (const float4*)g_x1 : (const float4*)g_x0;
    float4* xout = dir ? (float4*)g_x0 : (float4*)g_x1;
    int col = __ldg(&cols[e]);
    int row = __ldg(&rows[e]);
    float4 xv = __ldg(&xin[col * 16 + c]);
    float4 a = make_float4(v * xv.x, v * xv.y, v * xv.z, v * xv.w);
    atomicAdd(&xout[row * 16 + c], a);
}

// acc += (new buffer); optionally zero the other buffer for next layer.
// newbuf: 0 -> g_x0 holds new result, 1 -> g_x1 holds new result
__global__ void __launch_bounds__(256) k_acc(int newbuf, int do_zero) {
    int i = blockIdx.x * blockDim.x + threadIdx.x;
    if (i >= NODE_F4) return;
    float4* nb = newbuf ? (float4*)g_x1 : (float4*)g_x0;
    float4* ob = newbuf ? (float4*)g_x0 : (float4*)g_x1;
    float4 a = ((float4*)g_acc)[i];
    float4 b = nb[i];
    a.x += b.x; a.y += b.y; a.z += b.z; a.w += b.w;
    ((float4*)g_acc)[i] = a;
    if (do_zero) ob[i] = make_float4(0.f, 0.f, 0.f, 0.f);
}

// gather + target dropout. out layout: [u_online | u_target | i_online | i_target]
__global__ void __launch_bounds__(256) k_out(const int* __restrict__ users,
                                             const int* __restrict__ items,
                                             float* __restrict__ out,
                                             uint32_t ku0, uint32_t ku1,
                                             uint32_t ki0, uint32_t ki1) {
    int idx = blockIdx.x * blockDim.x + threadIdx.x;
    if (idx >= OUT_BLK) return;
    int b = idx >> 6;
    int d = idx & 63;
    float uval = g_acc[(long long)__ldg(&users[b]) * DIM + d] * 0.25f;
    float ival = g_acc[((long long)__ldg(&items[b]) + NUM_USER) * DIM + d] * 0.25f;
    // bernoulli keep iff uniform < 0.5 iff top bit clear; kept value / (1-p) = *2
    uint32_t bu = RBITS(ku0, ku1, idx, OUT_BLK);
    uint32_t bi = RBITS(ki0, ki1, idx, OUT_BLK);
    out[idx] = uval;
    out[OUT_BLK + idx] = (bu >> 31) ? 0.0f : uval * 2.0f;
    out[2 * OUT_BLK + idx] = ival;
    out[3 * OUT_BLK + idx] = (bi >> 31) ? 0.0f : ival * 2.0f;
}

// ---------------- launch ---------------------------------------------------
extern "C" void kernel_launch(void* const* d_in, const int* in_sizes, int n_in,
                              void* d_out, int out_size) {
    const float* user_emb = (const float*)d_in[0];
    const float* item_emb = (const float*)d_in[1];
    const float* adj_vals = (const float*)d_in[2];
    const int* adj_rows = (const int*)d_in[3];
    const int* adj_cols = (const int*)d_in[4];
    const int* users = (const int*)d_in[5];
    const int* items = (const int*)d_in[6];
    float* out = (float*)d_out;
    int n_edges = in_sizes[2];

    // key(1234) = (0, 1234); split into (ke, ku, ki)
    uint32_t ke0, ke1, ku0, ku1, ki0, ki1;
#if JAX_PARTITIONABLE
    // partitionable split: subkey_i = threefry(kd, (0, i))
    {
        uint32_t a, b;
        a = 0u; b = 0u; tf2x32(0u, 1234u, a, b); ke0 = a; ke1 = b;
        a = 0u; b = 1u; tf2x32(0u, 1234u, a, b); ku0 = a; ku1 = b;
        a = 0u; b = 2u; tf2x32(0u, 1234u, a, b); ki0 = a; ki1 = b;
    }
#else
    // original split: counts iota(6) -> halves [0,1,2],[3,4,5]; out=[a0,a1,a2,b0,b1,b2]
    {
        uint32_t a0 = 0u, b0 = 3u; tf2x32(0u, 1234u, a0, b0);
        uint32_t a1 = 1u, b1 = 4u; tf2x32(0u, 1234u, a1, b1);
        uint32_t a2 = 2u, b2 = 5u; tf2x32(0u, 1234u, a2, b2);
        ke0 = a0; ke1 = a1;
        ku0 = a2; ku1 = b0;
        ki0 = b1; ki1 = b2;
    }
#endif

    const int TPB = 256;
    const int TPB_S = 512;
    int nblk_nodes = (NODE_F4 + TPB - 1) / TPB;
    int nblk_edges = (n_edges + TPB - 1) / TPB;
    long long scat_threads = (long long)n_edges * 16;
    int nblk_scat = (int)((scat_threads + TPB_S - 1) / TPB_S);
    int nblk_out = (OUT_BLK + TPB - 1) / TPB;

    k_init<<<nblk_nodes, TPB>>>((const float4*)user_emb, (const float4*)item_emb);
    k_edges<<<nblk_edges, TPB>>>(adj_vals, n_edges, ke0, ke1);

    // layer 0: x0 -> x1 ; acc += x1 ; zero x0
    k_spmm<<<nblk_scat, TPB_S>>>(adj_rows, adj_cols, n_edges, 0);
    k_acc<<<nblk_nodes, TPB>>>(1, 1);
    // layer 1: x1 -> x0 ; acc += x0 ; zero x1
    k_spmm<<<nblk_scat, TPB_S>>>(adj_rows, adj_cols, n_edges, 1);
    k_acc<<<nblk_nodes, TPB>>>(0, 1);
    // layer 2: x0 -> x1 ; acc += x1
    k_spmm<<<nblk_scat, TPB_S>>>(adj_rows, adj_cols, n_edges, 0);
    k_acc<<<nblk_nodes, TPB>>>(1, 0);

    k_out<<<nblk_out, TPB>>>(users, items, out, ku0, ku1, ki0, ki1);
}

// round 16
// speedup vs baseline: 1.5926x; 1.5926x over previous
#include <cuda_runtime.h>
#include <stdint.h>

#define NUM_USER 200000
#define NUM_ITEM 100000
#define NUM_NODES 300000
#define DIM 64
#define BATCH 8192
#define NODE_FLOATS (NUM_NODES * DIM)     // 19,200,000 floats
#define NODE_F4 (NODE_FLOATS / 4)         // 4,800,000 float4
#define MAX_EDGES 2000000
#define OUT_BLK (BATCH * DIM)             // 524,288
#define CHUNK 16                          // edges per thread in sorted-half kernel

// ---------------- scratch (device globals; no cudaMalloc allowed) ----------
__device__ float g_x1[NODE_FLOATS];
__device__ float g_x2[NODE_FLOATS];
__device__ float g_x3[NODE_FLOATS];
__device__ float g_vals[MAX_EDGES];

// ---------------- threefry2x32 (exact JAX key schedule, partitionable) -----
#define TF_ROUND(x0, x1, r)                         \
    {                                               \
        x0 += x1;                                   \
        x1 = (x1 << (r)) | (x1 >> (32 - (r)));      \
        x1 ^= x0;                                   \
    }

__host__ __device__ __forceinline__ void tf2x32(uint32_t k0, uint32_t k1,
                                                uint32_t& x0, uint32_t& x1) {
    uint32_t k2 = k0 ^ k1 ^ 0x1BD11BDAu;
    x0 += k0; x1 += k1;
    TF_ROUND(x0, x1, 13) TF_ROUND(x0, x1, 15) TF_ROUND(x0, x1, 26) TF_ROUND(x0, x1, 6)
    x0 += k1; x1 += k2 + 1u;
    TF_ROUND(x0, x1, 17) TF_ROUND(x0, x1, 29) TF_ROUND(x0, x1, 16) TF_ROUND(x0, x1, 24)
    x0 += k2; x1 += k0 + 2u;
    TF_ROUND(x0, x1, 13) TF_ROUND(x0, x1, 15) TF_ROUND(x0, x1, 26) TF_ROUND(x0, x1, 6)
    x0 += k0; x1 += k1 + 3u;
    TF_ROUND(x0, x1, 17) TF_ROUND(x0, x1, 29) TF_ROUND(x0, x1, 16) TF_ROUND(x0, x1, 24)
    x0 += k1; x1 += k2 + 4u;
    TF_ROUND(x0, x1, 13) TF_ROUND(x0, x1, 15) TF_ROUND(x0, x1, 26) TF_ROUND(x0, x1, 6)
    x0 += k2; x1 += k0 + 5u;
}

__device__ __forceinline__ uint32_t rbits(uint32_t k0, uint32_t k1, uint32_t idx) {
    uint32_t x0 = 0u, x1 = idx;
    tf2x32(k0, k1, x0, x1);
    return x0 ^ x1;
}

// ---------------- device-side buffer selection (host must NOT take the
// address of __device__ globals — that was the R4 bug) ----------------------
__device__ __forceinline__ const float4* xin_buf(int sel) {
    // sel: 1 -> g_x1, 2 -> g_x2 (sel 0 = layer0, unused here)
    return (sel == 1) ? (const float4*)g_x1 : (const float4*)g_x2;
}
__device__ __forceinline__ float4* xout_buf(int sel) {
    // sel: 1 -> g_x1, 2 -> g_x2, 3 -> g_x3
    return (sel == 1) ? (float4*)g_x1 : (sel == 2) ? (float4*)g_x2 : (float4*)g_x3;
}

// ---------------- kernels --------------------------------------------------

// zero x1, x2, x3
__global__ void __launch_bounds__(256) k_zero() {
    int i = blockIdx.x * blockDim.x + threadIdx.x;
    if (i >= NODE_F4) return;
    float4 z = make_float4(0.f, 0.f, 0.f, 0.f);
    ((float4*)g_x1)[i] = z;
    ((float4*)g_x2)[i] = z;
    ((float4*)g_x3)[i] = z;
}

// edge dropout: keep iff uniform >= 0.5 iff top bit set; scale 1/(1-p)=2
__global__ void __launch_bounds__(256) k_edges(const float* __restrict__ adj_vals,
                                               int n_edges, uint32_t k0, uint32_t k1) {
    int e = blockIdx.x * blockDim.x + threadIdx.x;
    if (e >= n_edges) return;
    uint32_t bits = rbits(k0, k1, (uint32_t)e);
    g_vals[e] = (bits >> 31) ? __ldg(&adj_vals[e]) * 2.0f : 0.0f;
}

// gather source: in_sel==0 reads the raw embeddings (x0 is never materialized)
__device__ __forceinline__ float4 gather_x(int col, int c, int in_sel,
                                           const float4* __restrict__ ue,
                                           const float4* __restrict__ ie) {
    if (in_sel == 0)
        return (col < NUM_USER) ? __ldg(&ue[col * 16 + c])
                                : __ldg(&ie[(col - NUM_USER) * 16 + c]);
    return __ldg(&xin_buf(in_sel)[col * 16 + c]);
}

// SORTED half (rows non-decreasing): run-accumulate in registers, flush one
// atomic per row-run. 16 threads (float4 lanes) x CHUNK edges per thread-group.
__global__ void __launch_bounds__(256) k_spmm_sorted(
        const int* __restrict__ rows, const int* __restrict__ cols,
        const float4* __restrict__ ue, const float4* __restrict__ ie,
        int in_sel, int out_sel, int e_end) {
    int t = blockIdx.x * blockDim.x + threadIdx.x;
    int c = t & 15;
    int e0 = (t >> 4) * CHUNK;
    if (e0 >= e_end) return;
    int e1 = min(e0 + CHUNK, e_end);
    float4* xout = xout_buf(out_sel);
    float4 acc = make_float4(0.f, 0.f, 0.f, 0.f);
    int cur = -1;
    for (int e = e0; e < e1; e++) {
        float v = __ldg(&g_vals[e]);
        if (v == 0.0f) continue;
        int r = __ldg(&rows[e]);
        if (r != cur) {
            if (cur >= 0) atomicAdd(&xout[cur * 16 + c], acc);
            cur = r;
            acc = make_float4(0.f, 0.f, 0.f, 0.f);
        }
        float4 xv = gather_x(__ldg(&cols[e]), c, in_sel, ue, ie);
        acc.x += v * xv.x; acc.y += v * xv.y; acc.z += v * xv.z; acc.w += v * xv.w;
    }
    if (cur >= 0) atomicAdd(&xout[cur * 16 + c], acc);
}

// UNSORTED half: one float4 atomic per live edge-lane (16 lanes/edge)
__global__ void __launch_bounds__(512) k_spmm_plain(
        const int* __restrict__ rows, const int* __restrict__ cols,
        const float4* __restrict__ ue, const float4* __restrict__ ie,
        int in_sel, int out_sel, int e_begin, int e_end) {
    long long t = (long long)blockIdx.x * blockDim.x + threadIdx.x;
    int e = e_begin + (int)(t >> 4);
    if (e >= e_end) return;
    float v = __ldg(&g_vals[e]);
    if (v == 0.0f) return;
    int c = (int)(t & 15);
    float4 xv = gather_x(__ldg(&cols[e]), c, in_sel, ue, ie);
    float4 a = make_float4(v * xv.x, v * xv.y, v * xv.z, v * xv.w);
    atomicAdd(&xout_buf(out_sel)[__ldg(&rows[e]) * 16 + c], a);
}

// gather + (emb + x1 + x2 + x3)/4 + target dropout.
// out layout: [u_online | u_target | i_online | i_target]
__global__ void __launch_bounds__(256) k_out(const int* __restrict__ users,
                                             const int* __restrict__ items,
                                             const float* __restrict__ ue,
                                             const float* __restrict__ ie,
                                             float* __restrict__ out,
                                             uint32_t ku0, uint32_t ku1,
                                             uint32_t ki0, uint32_t ki1) {
    int idx = blockIdx.x * blockDim.x + threadIdx.x;
    if (idx >= OUT_BLK) return;
    int b = idx >> 6;
    int d = idx & 63;
    long long un = (long long)__ldg(&users[b]) * DIM + d;
    long long inode = (long long)__ldg(&items[b]);
    long long inn = (inode + NUM_USER) * DIM + d;
    float uval = (__ldg(&ue[un]) + g_x1[un] + g_x2[un] + g_x3[un]) * 0.25f;
    float ival = (__ldg(&ie[inode * DIM + d]) + g_x1[inn] + g_x2[inn] + g_x3[inn]) * 0.25f;
    // bernoulli keep iff uniform < 0.5 iff top bit clear; kept value * 2
    uint32_t bu = rbits(ku0, ku1, (uint32_t)idx);
    uint32_t bi = rbits(ki0, ki1, (uint32_t)idx);
    out[idx] = uval;
    out[OUT_BLK + idx] = (bu >> 31) ? 0.0f : uval * 2.0f;
    out[2 * OUT_BLK + idx] = ival;
    out[3 * OUT_BLK + idx] = (bi >> 31) ? 0.0f : ival * 2.0f;
}

// ---------------- launch ---------------------------------------------------
extern "C" void kernel_launch(void* const* d_in, const int* in_sizes, int n_in,
                              void* d_out, int out_size) {
    const float* user_emb = (const float*)d_in[0];
    const float* item_emb = (const float*)d_in[1];
    const float* adj_vals = (const float*)d_in[2];
    const int* adj_rows = (const int*)d_in[3];
    const int* adj_cols = (const int*)d_in[4];
    const int* users = (const int*)d_in[5];
    const int* items = (const int*)d_in[6];
    float* out = (float*)d_out;
    int n_edges = in_sizes[2];
    int n_half = n_edges / 2;   // first half: rows = u, sorted non-decreasing

    // key(1234) = (0, 1234); partitionable split: subkey_i = threefry(kd, (0, i))
    uint32_t ke0, ke1, ku0, ku1, ki0, ki1;
    {
        uint32_t a, b;
        a = 0u; b = 0u; tf2x32(0u, 1234u, a, b); ke0 = a; ke1 = b;
        a = 0u; b = 1u; tf2x32(0u, 1234u, a, b); ku0 = a; ku1 = b;
        a = 0u; b = 2u; tf2x32(0u, 1234u, a, b); ki0 = a; ki1 = b;
    }

    const float4* ue4 = (const float4*)user_emb;
    const float4* ie4 = (const float4*)item_emb;
    const int TPB = 256;
    const int TPB_P = 512;
    int nblk_nodes = (NODE_F4 + TPB - 1) / TPB;
    int nblk_edges = (n_edges + TPB - 1) / TPB;
    long long sorted_threads = ((long long)(n_half + CHUNK - 1) / CHUNK) * 16;
    int nblk_sorted = (int)((sorted_threads + TPB - 1) / TPB);
    long long plain_threads = (long long)(n_edges - n_half) * 16;
    int nblk_plain = (int)((plain_threads + TPB_P - 1) / TPB_P);
    int nblk_out = (OUT_BLK + TPB - 1) / TPB;

    k_zero<<<nblk_nodes, TPB>>>();
    k_edges<<<nblk_edges, TPB>>>(adj_vals, n_edges, ke0, ke1);

    // layer 1: emb (in_sel 0) -> x1
    k_spmm_sorted<<<nblk_sorted, TPB>>>(adj_rows, adj_cols, ue4, ie4, 0, 1, n_half);
    k_spmm_plain<<<nblk_plain, TPB_P>>>(adj_rows, adj_cols, ue4, ie4, 0, 1,
                                        n_half, n_edges);
    // layer 2: x1 -> x2
    k_spmm_sorted<<<nblk_sorted, TPB>>>(adj_rows, adj_cols, ue4, ie4, 1, 2, n_half);
    k_spmm_plain<<<nblk_plain, TPB_P>>>(adj_rows, adj_cols, ue4, ie4, 1, 2,
                                        n_half, n_edges);
    // layer 3: x2 -> x3
    k_spmm_sorted<<<nblk_sorted, TPB>>>(adj_rows, adj_cols, ue4, ie4, 2, 3, n_half);
    k_spmm_plain<<<nblk_plain, TPB_P>>>(adj_rows, adj_cols, ue4, ie4, 2, 3,
                                        n_half, n_edges);

    k_out<<<nblk_out, TPB>>>(users, items, user_emb, item_emb, out,
                             ku0, ku1, ki0, ki1);
}